// round 9
// baseline (speedup 1.0000x reference)
#include <cuda_runtime.h>

// Problem constants
#define B_ 8
#define L_ 2048
#define H_ 256

// Scratch (device globals — no allocations allowed)
__device__ float d_Wh[B_ * L_ * H_];                     // 16.8 MB
__device__ float d_S[(long long)B_ * L_ * L_];           // 134 MB
__device__ float d_c[B_ * L_ * H_];                      // 16.8 MB
__device__ float d_m[B_ * L_];
__device__ float d_invZ[B_ * L_];

// ---------------------------------------------------------------------------
// Generic NT SGEMM: C[M,N] = A[M,K] * Bt[N,K]^T   (both A and Bt K-contiguous)
// 128x128 block tile, BK=8, 256 threads, 8x8 per thread. All dims % tile == 0.
// ---------------------------------------------------------------------------
__global__ __launch_bounds__(256) void sgemm_nt(
    const float* __restrict__ A, const float* __restrict__ Bt,
    float* __restrict__ C, int M, int N, int K,
    long long sA, long long sB, long long sC)
{
    A  += (long long)blockIdx.z * sA;
    Bt += (long long)blockIdx.z * sB;
    C  += (long long)blockIdx.z * sC;

    __shared__ __align__(16) float As[8][128];
    __shared__ __align__(16) float Bs[8][128];

    const int tid   = threadIdx.x;
    const int mBase = blockIdx.y * 128;
    const int nBase = blockIdx.x * 128;
    const int lr = tid >> 1;            // 0..127 (tile row for loads)
    const int lc = (tid & 1) << 2;      // 0 or 4 (k offset for loads)
    const int m0 = (tid >> 4) << 3;     // thread micro-tile row
    const int n0 = (tid & 15) << 3;     // thread micro-tile col

    float acc[8][8];
    #pragma unroll
    for (int i = 0; i < 8; ++i)
        #pragma unroll
        for (int j = 0; j < 8; ++j) acc[i][j] = 0.f;

    for (int k0 = 0; k0 < K; k0 += 8) {
        float4 av = *(const float4*)&A [(long long)(mBase + lr) * K + (k0 + lc)];
        float4 bv = *(const float4*)&Bt[(long long)(nBase + lr) * K + (k0 + lc)];
        As[lc + 0][lr] = av.x; As[lc + 1][lr] = av.y;
        As[lc + 2][lr] = av.z; As[lc + 3][lr] = av.w;
        Bs[lc + 0][lr] = bv.x; Bs[lc + 1][lr] = bv.y;
        Bs[lc + 2][lr] = bv.z; Bs[lc + 3][lr] = bv.w;
        __syncthreads();
        #pragma unroll
        for (int kk = 0; kk < 8; ++kk) {
            float4 a0 = *(const float4*)&As[kk][m0];
            float4 a1 = *(const float4*)&As[kk][m0 + 4];
            float4 b0 = *(const float4*)&Bs[kk][n0];
            float4 b1 = *(const float4*)&Bs[kk][n0 + 4];
            float a[8] = {a0.x, a0.y, a0.z, a0.w, a1.x, a1.y, a1.z, a1.w};
            float b[8] = {b0.x, b0.y, b0.z, b0.w, b1.x, b1.y, b1.z, b1.w};
            #pragma unroll
            for (int i = 0; i < 8; ++i)
                #pragma unroll
                for (int j = 0; j < 8; ++j)
                    acc[i][j] = fmaf(a[i], b[j], acc[i][j]);
        }
        __syncthreads();
    }

    #pragma unroll
    for (int i = 0; i < 8; ++i) {
        float* crow = &C[(long long)(mBase + m0 + i) * N + nBase + n0];
        *(float4*)&crow[0] = make_float4(acc[i][0], acc[i][1], acc[i][2], acc[i][3]);
        *(float4*)&crow[4] = make_float4(acc[i][4], acc[i][5], acc[i][6], acc[i][7]);
    }
}

// ---------------------------------------------------------------------------
// Column softmax stats over dim i: for each (b,j): m_j = max_i S[i,j],
// Z_j = sum_i exp(S[i,j]-m_j). Online single pass, coalesced (thread = col j).
// ---------------------------------------------------------------------------
__global__ void colstats_kernel()
{
    const int col = blockIdx.x * blockDim.x + threadIdx.x;   // 0..B*L-1
    const int b = col >> 11;            // / 2048
    const int j = col & (L_ - 1);
    const float* Sp = d_S + (long long)b * L_ * L_ + j;

    float m = -3.4e38f, Z = 0.f;
    #pragma unroll 4
    for (int i = 0; i < L_; ++i) {
        float x  = Sp[(long long)i * L_];
        float mn = fmaxf(m, x);
        Z = Z * __expf(m - mn) + __expf(x - mn);
        m = mn;
    }
    d_m[col]    = m;
    d_invZ[col] = 1.f / Z;
}

// ---------------------------------------------------------------------------
// c[b,i,h] = sum_j P[i,j] * g[b,j,h],  P[i,j] = exp(S[i,j]-m_j) * invZ_j
// NN GEMM (M=L, N=H, K=L) with the exp transform fused into the A-tile load.
// ---------------------------------------------------------------------------
__global__ __launch_bounds__(256) void attn_c_kernel(const float* __restrict__ g)
{
    const int b = blockIdx.z;
    const float* S     = d_S + (long long)b * L_ * L_;
    const float* gb    = g   + (long long)b * L_ * H_;
    float*       cb    = d_c + (long long)b * L_ * H_;
    const float* mcol  = d_m    + b * L_;
    const float* izcol = d_invZ + b * L_;

    __shared__ __align__(16) float As[8][128];
    __shared__ __align__(16) float Bs[8][128];

    const int tid   = threadIdx.x;
    const int mBase = blockIdx.y * 128;
    const int nBase = blockIdx.x * 128;
    const int lr = tid >> 1;
    const int lc = (tid & 1) << 2;
    const int kr = tid >> 5;            // 0..7  (B tile row)
    const int c4 = (tid & 31) << 2;     // 0..124 (B tile col)
    const int m0 = (tid >> 4) << 3;
    const int n0 = (tid & 15) << 3;

    float acc[8][8];
    #pragma unroll
    for (int i = 0; i < 8; ++i)
        #pragma unroll
        for (int j = 0; j < 8; ++j) acc[i][j] = 0.f;

    for (int k0 = 0; k0 < L_; k0 += 8) {
        const int j = k0 + lc;
        float4 av = *(const float4*)&S[(long long)(mBase + lr) * L_ + j];
        av.x = __expf(av.x - mcol[j + 0]) * izcol[j + 0];
        av.y = __expf(av.y - mcol[j + 1]) * izcol[j + 1];
        av.z = __expf(av.z - mcol[j + 2]) * izcol[j + 2];
        av.w = __expf(av.w - mcol[j + 3]) * izcol[j + 3];
        As[lc + 0][lr] = av.x; As[lc + 1][lr] = av.y;
        As[lc + 2][lr] = av.z; As[lc + 3][lr] = av.w;
        *(float4*)&Bs[kr][c4] =
            *(const float4*)&gb[(long long)(k0 + kr) * H_ + nBase + c4];
        __syncthreads();
        #pragma unroll
        for (int kk = 0; kk < 8; ++kk) {
            float4 a0 = *(const float4*)&As[kk][m0];
            float4 a1 = *(const float4*)&As[kk][m0 + 4];
            float4 b0 = *(const float4*)&Bs[kk][n0];
            float4 b1 = *(const float4*)&Bs[kk][n0 + 4];
            float a[8] = {a0.x, a0.y, a0.z, a0.w, a1.x, a1.y, a1.z, a1.w};
            float bb[8] = {b0.x, b0.y, b0.z, b0.w, b1.x, b1.y, b1.z, b1.w};
            #pragma unroll
            for (int i = 0; i < 8; ++i)
                #pragma unroll
                for (int jj = 0; jj < 8; ++jj)
                    acc[i][jj] = fmaf(a[i], bb[jj], acc[i][jj]);
        }
        __syncthreads();
    }

    #pragma unroll
    for (int i = 0; i < 8; ++i) {
        float* crow = &cb[(long long)(mBase + m0 + i) * H_ + nBase + n0];
        *(float4*)&crow[0] = make_float4(acc[i][0], acc[i][1], acc[i][2], acc[i][3]);
        *(float4*)&crow[4] = make_float4(acc[i][4], acc[i][5], acc[i][6], acc[i][7]);
    }
}

// ---------------------------------------------------------------------------
// out[m,o] = relu( sum_k cat[m,k] * W_out[o,k] + b_out[o] ),  K = 768.
// cat[m,k] synthesized on the fly: k<256 -> g, k<512 -> c, else g*c.
// (BK=8 tiles never straddle the 256-aligned segment boundaries.)
// ---------------------------------------------------------------------------
__global__ __launch_bounds__(256) void final_kernel(
    const float* __restrict__ g, const float* __restrict__ Wout,
    const float* __restrict__ bout, float* __restrict__ out)
{
    const int K = 3 * H_;   // 768
    const int N = H_;       // 256

    __shared__ __align__(16) float As[8][128];
    __shared__ __align__(16) float Bs[8][128];

    const int tid   = threadIdx.x;
    const int mBase = blockIdx.y * 128;
    const int nBase = blockIdx.x * 128;
    const int lr = tid >> 1;
    const int lc = (tid & 1) << 2;
    const int m0 = (tid >> 4) << 3;
    const int n0 = (tid & 15) << 3;

    float acc[8][8];
    #pragma unroll
    for (int i = 0; i < 8; ++i)
        #pragma unroll
        for (int j = 0; j < 8; ++j) acc[i][j] = 0.f;

    for (int k0 = 0; k0 < K; k0 += 8) {
        const int kg  = k0 + lc;
        const int seg = kg >> 8;
        const int kk  = kg & 255;
        const long long rowoff = (long long)(mBase + lr) * H_ + kk;
        float4 v;
        if (seg == 0) {
            v = *(const float4*)&g[rowoff];
        } else if (seg == 1) {
            v = *(const float4*)&d_c[rowoff];
        } else {
            float4 gv = *(const float4*)&g[rowoff];
            float4 cv = *(const float4*)&d_c[rowoff];
            v = make_float4(gv.x * cv.x, gv.y * cv.y, gv.z * cv.z, gv.w * cv.w);
        }
        As[lc + 0][lr] = v.x; As[lc + 1][lr] = v.y;
        As[lc + 2][lr] = v.z; As[lc + 3][lr] = v.w;
        float4 bv = *(const float4*)&Wout[(long long)(nBase + lr) * K + kg];
        Bs[lc + 0][lr] = bv.x; Bs[lc + 1][lr] = bv.y;
        Bs[lc + 2][lr] = bv.z; Bs[lc + 3][lr] = bv.w;
        __syncthreads();
        #pragma unroll
        for (int kq = 0; kq < 8; ++kq) {
            float4 a0 = *(const float4*)&As[kq][m0];
            float4 a1 = *(const float4*)&As[kq][m0 + 4];
            float4 b0 = *(const float4*)&Bs[kq][n0];
            float4 b1 = *(const float4*)&Bs[kq][n0 + 4];
            float a[8] = {a0.x, a0.y, a0.z, a0.w, a1.x, a1.y, a1.z, a1.w};
            float b[8] = {b0.x, b0.y, b0.z, b0.w, b1.x, b1.y, b1.z, b1.w};
            #pragma unroll
            for (int i = 0; i < 8; ++i)
                #pragma unroll
                for (int j = 0; j < 8; ++j)
                    acc[i][j] = fmaf(a[i], b[j], acc[i][j]);
        }
        __syncthreads();
    }

    float bj[8];
    #pragma unroll
    for (int j = 0; j < 8; ++j) bj[j] = bout[nBase + n0 + j];

    #pragma unroll
    for (int i = 0; i < 8; ++i) {
        float* orow = &out[(long long)(mBase + m0 + i) * N + nBase + n0];
        float r[8];
        #pragma unroll
        for (int j = 0; j < 8; ++j) r[j] = fmaxf(acc[i][j] + bj[j], 0.f);
        *(float4*)&orow[0] = make_float4(r[0], r[1], r[2], r[3]);
        *(float4*)&orow[4] = make_float4(r[4], r[5], r[6], r[7]);
    }
}

// ---------------------------------------------------------------------------
// Launch: 5 kernels on the default stream (graph-capturable, allocation-free)
// ---------------------------------------------------------------------------
extern "C" void kernel_launch(void* const* d_in, const int* in_sizes, int n_in,
                              void* d_out, int out_size)
{
    const float* g     = (const float*)d_in[0];
    const float* WP    = (const float*)d_in[1];
    const float* W_out = (const float*)d_in[2];
    const float* b_out = (const float*)d_in[3];
    float* out = (float*)d_out;

    void* pWh = nullptr;
    void* pS  = nullptr;
    cudaGetSymbolAddress(&pWh, d_Wh);
    cudaGetSymbolAddress(&pS, d_S);

    dim3 blk(256);

    // K1: Wh = g @ WP^T            M=16384, N=256, K=256
    sgemm_nt<<<dim3(H_ / 128, (B_ * L_) / 128, 1), blk>>>(
        g, WP, (float*)pWh, B_ * L_, H_, H_, 0, 0, 0);

    // K2: S_b = Wh_b @ g_b^T       per batch: M=N=2048, K=256
    sgemm_nt<<<dim3(L_ / 128, L_ / 128, B_), blk>>>(
        (float*)pWh, g, (float*)pS, L_, L_, H_,
        (long long)L_ * H_, (long long)L_ * H_, (long long)L_ * L_);

    // K3: per-column softmax stats (max + sumexp over dim i)
    colstats_kernel<<<(B_ * L_) / 256, 256>>>();

    // K4: c_b = softmax(S_b) @ g_b    per batch: M=2048, N=256, K=2048
    attn_c_kernel<<<dim3(H_ / 128, L_ / 128, B_), blk>>>(g);

    // K5: out = relu(concat(g,c,g*c) @ W_out^T + b_out)
    final_kernel<<<dim3(H_ / 128, (B_ * L_) / 128, 1), blk>>>(g, W_out, b_out, out);
}

// round 10
// speedup vs baseline: 1.0059x; 1.0059x over previous
#include <cuda_runtime.h>

// Problem constants
#define B_ 8
#define L_ 2048
#define H_ 256

// Scratch (device globals — no allocations allowed)
__device__ float d_Wh[B_ * L_ * H_];                     // 16.8 MB
__device__ float d_S[(long long)B_ * L_ * L_];           // 134 MB
__device__ float d_c[B_ * L_ * H_];                      // 16.8 MB
__device__ float d_m[B_ * L_];
__device__ float d_invZ[B_ * L_];

// ---------------------------------------------------------------------------
// Generic NT SGEMM: C[M,N] = A[M,K] * Bt[N,K]^T   (both A and Bt K-contiguous)
// 128x128 block tile, BK=8, 256 threads, 8x8 per thread. All dims % tile == 0.
// ---------------------------------------------------------------------------
__global__ __launch_bounds__(256) void sgemm_nt(
    const float* __restrict__ A, const float* __restrict__ Bt,
    float* __restrict__ C, int M, int N, int K,
    long long sA, long long sB, long long sC)
{
    A  += (long long)blockIdx.z * sA;
    Bt += (long long)blockIdx.z * sB;
    C  += (long long)blockIdx.z * sC;

    __shared__ __align__(16) float As[8][128];
    __shared__ __align__(16) float Bs[8][128];

    const int tid   = threadIdx.x;
    const int mBase = blockIdx.y * 128;
    const int nBase = blockIdx.x * 128;
    const int lr = tid >> 1;            // 0..127 (tile row for loads)
    const int lc = (tid & 1) << 2;      // 0 or 4 (k offset for loads)
    const int m0 = (tid >> 4) << 3;     // thread micro-tile row
    const int n0 = (tid & 15) << 3;     // thread micro-tile col

    float acc[8][8];
    #pragma unroll
    for (int i = 0; i < 8; ++i)
        #pragma unroll
        for (int j = 0; j < 8; ++j) acc[i][j] = 0.f;

    for (int k0 = 0; k0 < K; k0 += 8) {
        float4 av = *(const float4*)&A [(long long)(mBase + lr) * K + (k0 + lc)];
        float4 bv = *(const float4*)&Bt[(long long)(nBase + lr) * K + (k0 + lc)];
        As[lc + 0][lr] = av.x; As[lc + 1][lr] = av.y;
        As[lc + 2][lr] = av.z; As[lc + 3][lr] = av.w;
        Bs[lc + 0][lr] = bv.x; Bs[lc + 1][lr] = bv.y;
        Bs[lc + 2][lr] = bv.z; Bs[lc + 3][lr] = bv.w;
        __syncthreads();
        #pragma unroll
        for (int kk = 0; kk < 8; ++kk) {
            float4 a0 = *(const float4*)&As[kk][m0];
            float4 a1 = *(const float4*)&As[kk][m0 + 4];
            float4 b0 = *(const float4*)&Bs[kk][n0];
            float4 b1 = *(const float4*)&Bs[kk][n0 + 4];
            float a[8] = {a0.x, a0.y, a0.z, a0.w, a1.x, a1.y, a1.z, a1.w};
            float b[8] = {b0.x, b0.y, b0.z, b0.w, b1.x, b1.y, b1.z, b1.w};
            #pragma unroll
            for (int i = 0; i < 8; ++i)
                #pragma unroll
                for (int j = 0; j < 8; ++j)
                    acc[i][j] = fmaf(a[i], b[j], acc[i][j]);
        }
        __syncthreads();
    }

    #pragma unroll
    for (int i = 0; i < 8; ++i) {
        float* crow = &C[(long long)(mBase + m0 + i) * N + nBase + n0];
        *(float4*)&crow[0] = make_float4(acc[i][0], acc[i][1], acc[i][2], acc[i][3]);
        *(float4*)&crow[4] = make_float4(acc[i][4], acc[i][5], acc[i][6], acc[i][7]);
    }
}

// ---------------------------------------------------------------------------
// Column softmax stats over dim i: for each (b,j): m_j = max_i S[i,j],
// Z_j = sum_i exp(S[i,j]-m_j). Online single pass, coalesced (thread = col j).
// ---------------------------------------------------------------------------
__global__ void colstats_kernel()
{
    const int col = blockIdx.x * blockDim.x + threadIdx.x;   // 0..B*L-1
    const int b = col >> 11;            // / 2048
    const int j = col & (L_ - 1);
    const float* Sp = d_S + (long long)b * L_ * L_ + j;

    float m = -3.4e38f, Z = 0.f;
    #pragma unroll 4
    for (int i = 0; i < L_; ++i) {
        float x  = Sp[(long long)i * L_];
        float mn = fmaxf(m, x);
        Z = Z * __expf(m - mn) + __expf(x - mn);
        m = mn;
    }
    d_m[col]    = m;
    d_invZ[col] = 1.f / Z;
}

// ---------------------------------------------------------------------------
// c[b,i,h] = sum_j P[i,j] * g[b,j,h],  P[i,j] = exp(S[i,j]-m_j) * invZ_j
// NN GEMM (M=L, N=H, K=L) with the exp transform fused into the A-tile load.
// ---------------------------------------------------------------------------
__global__ __launch_bounds__(256) void attn_c_kernel(const float* __restrict__ g)
{
    const int b = blockIdx.z;
    const float* S     = d_S + (long long)b * L_ * L_;
    const float* gb    = g   + (long long)b * L_ * H_;
    float*       cb    = d_c + (long long)b * L_ * H_;
    const float* mcol  = d_m    + b * L_;
    const float* izcol = d_invZ + b * L_;

    __shared__ __align__(16) float As[8][128];
    __shared__ __align__(16) float Bs[8][128];

    const int tid   = threadIdx.x;
    const int mBase = blockIdx.y * 128;
    const int nBase = blockIdx.x * 128;
    const int lr = tid >> 1;
    const int lc = (tid & 1) << 2;
    const int kr = tid >> 5;            // 0..7  (B tile row)
    const int c4 = (tid & 31) << 2;     // 0..124 (B tile col)
    const int m0 = (tid >> 4) << 3;
    const int n0 = (tid & 15) << 3;

    float acc[8][8];
    #pragma unroll
    for (int i = 0; i < 8; ++i)
        #pragma unroll
        for (int j = 0; j < 8; ++j) acc[i][j] = 0.f;

    for (int k0 = 0; k0 < L_; k0 += 8) {
        const int j = k0 + lc;
        float4 av = *(const float4*)&S[(long long)(mBase + lr) * L_ + j];
        av.x = __expf(av.x - mcol[j + 0]) * izcol[j + 0];
        av.y = __expf(av.y - mcol[j + 1]) * izcol[j + 1];
        av.z = __expf(av.z - mcol[j + 2]) * izcol[j + 2];
        av.w = __expf(av.w - mcol[j + 3]) * izcol[j + 3];
        As[lc + 0][lr] = av.x; As[lc + 1][lr] = av.y;
        As[lc + 2][lr] = av.z; As[lc + 3][lr] = av.w;
        *(float4*)&Bs[kr][c4] =
            *(const float4*)&gb[(long long)(k0 + kr) * H_ + nBase + c4];
        __syncthreads();
        #pragma unroll
        for (int kk = 0; kk < 8; ++kk) {
            float4 a0 = *(const float4*)&As[kk][m0];
            float4 a1 = *(const float4*)&As[kk][m0 + 4];
            float4 b0 = *(const float4*)&Bs[kk][n0];
            float4 b1 = *(const float4*)&Bs[kk][n0 + 4];
            float a[8] = {a0.x, a0.y, a0.z, a0.w, a1.x, a1.y, a1.z, a1.w};
            float bb[8] = {b0.x, b0.y, b0.z, b0.w, b1.x, b1.y, b1.z, b1.w};
            #pragma unroll
            for (int i = 0; i < 8; ++i)
                #pragma unroll
                for (int jj = 0; jj < 8; ++jj)
                    acc[i][jj] = fmaf(a[i], bb[jj], acc[i][jj]);
        }
        __syncthreads();
    }

    #pragma unroll
    for (int i = 0; i < 8; ++i) {
        float* crow = &cb[(long long)(mBase + m0 + i) * H_ + nBase + n0];
        *(float4*)&crow[0] = make_float4(acc[i][0], acc[i][1], acc[i][2], acc[i][3]);
        *(float4*)&crow[4] = make_float4(acc[i][4], acc[i][5], acc[i][6], acc[i][7]);
    }
}

// ---------------------------------------------------------------------------
// out[m,o] = relu( sum_k cat[m,k] * W_out[o,k] + b_out[o] ),  K = 768.
// cat[m,k] synthesized on the fly: k<256 -> g, k<512 -> c, else g*c.
// (BK=8 tiles never straddle the 256-aligned segment boundaries.)
// ---------------------------------------------------------------------------
__global__ __launch_bounds__(256) void final_kernel(
    const float* __restrict__ g, const float* __restrict__ Wout,
    const float* __restrict__ bout, float* __restrict__ out)
{
    const int K = 3 * H_;   // 768
    const int N = H_;       // 256

    __shared__ __align__(16) float As[8][128];
    __shared__ __align__(16) float Bs[8][128];

    const int tid   = threadIdx.x;
    const int mBase = blockIdx.y * 128;
    const int nBase = blockIdx.x * 128;
    const int lr = tid >> 1;
    const int lc = (tid & 1) << 2;
    const int m0 = (tid >> 4) << 3;
    const int n0 = (tid & 15) << 3;

    float acc[8][8];
    #pragma unroll
    for (int i = 0; i < 8; ++i)
        #pragma unroll
        for (int j = 0; j < 8; ++j) acc[i][j] = 0.f;

    for (int k0 = 0; k0 < K; k0 += 8) {
        const int kg  = k0 + lc;
        const int seg = kg >> 8;
        const int kk  = kg & 255;
        const long long rowoff = (long long)(mBase + lr) * H_ + kk;
        float4 v;
        if (seg == 0) {
            v = *(const float4*)&g[rowoff];
        } else if (seg == 1) {
            v = *(const float4*)&d_c[rowoff];
        } else {
            float4 gv = *(const float4*)&g[rowoff];
            float4 cv = *(const float4*)&d_c[rowoff];
            v = make_float4(gv.x * cv.x, gv.y * cv.y, gv.z * cv.z, gv.w * cv.w);
        }
        As[lc + 0][lr] = v.x; As[lc + 1][lr] = v.y;
        As[lc + 2][lr] = v.z; As[lc + 3][lr] = v.w;
        float4 bv = *(const float4*)&Wout[(long long)(nBase + lr) * K + kg];
        Bs[lc + 0][lr] = bv.x; Bs[lc + 1][lr] = bv.y;
        Bs[lc + 2][lr] = bv.z; Bs[lc + 3][lr] = bv.w;
        __syncthreads();
        #pragma unroll
        for (int kq = 0; kq < 8; ++kq) {
            float4 a0 = *(const float4*)&As[kq][m0];
            float4 a1 = *(const float4*)&As[kq][m0 + 4];
            float4 b0 = *(const float4*)&Bs[kq][n0];
            float4 b1 = *(const float4*)&Bs[kq][n0 + 4];
            float a[8] = {a0.x, a0.y, a0.z, a0.w, a1.x, a1.y, a1.z, a1.w};
            float b[8] = {b0.x, b0.y, b0.z, b0.w, b1.x, b1.y, b1.z, b1.w};
            #pragma unroll
            for (int i = 0; i < 8; ++i)
                #pragma unroll
                for (int j = 0; j < 8; ++j)
                    acc[i][j] = fmaf(a[i], b[j], acc[i][j]);
        }
        __syncthreads();
    }

    float bj[8];
    #pragma unroll
    for (int j = 0; j < 8; ++j) bj[j] = bout[nBase + n0 + j];

    #pragma unroll
    for (int i = 0; i < 8; ++i) {
        float* orow = &out[(long long)(mBase + m0 + i) * N + nBase + n0];
        float r[8];
        #pragma unroll
        for (int j = 0; j < 8; ++j) r[j] = fmaxf(acc[i][j] + bj[j], 0.f);
        *(float4*)&orow[0] = make_float4(r[0], r[1], r[2], r[3]);
        *(float4*)&orow[4] = make_float4(r[4], r[5], r[6], r[7]);
    }
}

// ---------------------------------------------------------------------------
// Launch: 5 kernels on the default stream (graph-capturable, allocation-free)
// ---------------------------------------------------------------------------
extern "C" void kernel_launch(void* const* d_in, const int* in_sizes, int n_in,
                              void* d_out, int out_size)
{
    const float* g     = (const float*)d_in[0];
    const float* WP    = (const float*)d_in[1];
    const float* W_out = (const float*)d_in[2];
    const float* b_out = (const float*)d_in[3];
    float* out = (float*)d_out;

    void* pWh = nullptr;
    void* pS  = nullptr;
    cudaGetSymbolAddress(&pWh, d_Wh);
    cudaGetSymbolAddress(&pS, d_S);

    dim3 blk(256);

    // K1: Wh = g @ WP^T            M=16384, N=256, K=256
    sgemm_nt<<<dim3(H_ / 128, (B_ * L_) / 128, 1), blk>>>(
        g, WP, (float*)pWh, B_ * L_, H_, H_, 0, 0, 0);

    // K2: S_b = Wh_b @ g_b^T       per batch: M=N=2048, K=256
    sgemm_nt<<<dim3(L_ / 128, L_ / 128, B_), blk>>>(
        (float*)pWh, g, (float*)pS, L_, L_, H_,
        (long long)L_ * H_, (long long)L_ * H_, (long long)L_ * L_);

    // K3: per-column softmax stats (max + sumexp over dim i)
    colstats_kernel<<<(B_ * L_) / 256, 256>>>();

    // K4: c_b = softmax(S_b) @ g_b    per batch: M=2048, N=256, K=2048
    attn_c_kernel<<<dim3(H_ / 128, L_ / 128, B_), blk>>>(g);

    // K5: out = relu(concat(g,c,g*c) @ W_out^T + b_out)
    final_kernel<<<dim3(H_ / 128, (B_ * L_) / 128, 1), blk>>>(g, W_out, b_out, out);
}